// round 9
// baseline (speedup 1.0000x reference)
#include <cuda_runtime.h>
#include <cuda_fp16.h>

// ---------------------------------------------------------------------------
// GAT encoder: 2x GATConv (4 heads x 32, then 1 head x 256), ReLU between.
// R8 (= R7 fixed): vectorized CSR build (int4 edge loads, self-loops folded
//     into scan), GEMM1 reads fp32 x directly, GEMM2-c0 overlapped with
//     gather1-c1, gather1 MLP=8. HMMA GEMMs, fused single-pass gathers.
// ---------------------------------------------------------------------------

#define NNODES 50000
#define EMAX   1700000   // >= E + N

__device__ __align__(16) __half g_wt1h[128 * 128];
__device__ __align__(16) __half g_wt2h[256 * 128];
__device__ __align__(16) __half g_hlin1[NNODES * 128];
__device__ __align__(16) float  g_als1[NNODES * 4];
__device__ __align__(16) float  g_ald1[NNODES * 4];
__device__ __align__(16) __half g_agg1h[NNODES * 128];
__device__ __align__(16) __half g_hlin2[NNODES * 256];
__device__ __align__(16) float  g_als2[NNODES];
__device__ __align__(16) float  g_ald2[NNODES];
__device__ int g_count[NNODES];
__device__ int g_rowstart[NNODES + 1];
__device__ int g_cursor[NNODES];
__device__ int g_sorted_src[EMAX];

__device__ __forceinline__ float lrelu(float x) {
    return x > 0.0f ? x : 0.2f * x;
}

// ---------------------------------------------------------------------------
// Weight conversion (both layers in one launch)
// ---------------------------------------------------------------------------
__global__ void cvt_wts(const float* __restrict__ W1, __half* __restrict__ WT1,
                        const float* __restrict__ W2, __half* __restrict__ WT2) {
    int i = blockIdx.x * blockDim.x + threadIdx.x;
    if (i < 128 * 128) {
        int n = i >> 7, k = i & 127;
        WT1[i] = __float2half(W1[k * 128 + n]);
    } else if (i < 128 * 128 + 256 * 128) {
        int j = i - 128 * 128;
        int n = j >> 7, k = j & 127;
        WT2[j] = __float2half(W2[k * 256 + n]);
    }
}

// ---------------------------------------------------------------------------
// CSR build (vectorized). Self-loops handled as +1 per node inside the scan.
// ---------------------------------------------------------------------------
__global__ void hist_dst_v(const int* __restrict__ ei, int E,
                           int* __restrict__ cnt) {
    int i = blockIdx.x * blockDim.x + threadIdx.x;
    int nv = E >> 2;
    if (i < nv) {
        int4 d4 = *(const int4*)&ei[E + i * 4];
        atomicAdd(&cnt[d4.x], 1);
        atomicAdd(&cnt[d4.y], 1);
        atomicAdd(&cnt[d4.z], 1);
        atomicAdd(&cnt[d4.w], 1);
    } else {
        int e = nv * 4 + (i - nv);      // tail edges (E not multiple of 4)
        if (e < E) atomicAdd(&cnt[ei[E + e]], 1);
    }
}

// exclusive scan of (cnt[i] + 1)  -- the +1 is each node's self loop.
__global__ __launch_bounds__(1024, 1)
void scan_counts(const int* __restrict__ cnt, int* __restrict__ rowstart,
                 int* __restrict__ cursor, int N) {
    __shared__ int wsum[32];
    __shared__ int s_carry;
    const int tid = threadIdx.x, lane = tid & 31, wid = tid >> 5;
    if (tid == 0) s_carry = 0;
    __syncthreads();
    for (int base = 0; base < N; base += 4096) {
        int idx = base + tid * 4;
        int4 v = make_int4(-1, -1, -1, -1);   // -1 + 1 = 0 for out-of-range
        if (idx + 3 < N) v = *(const int4*)&cnt[idx];
        else {
            if (idx + 0 < N) v.x = cnt[idx + 0];
            if (idx + 1 < N) v.y = cnt[idx + 1];
            if (idx + 2 < N) v.z = cnt[idx + 2];
            if (idx + 3 < N) v.w = cnt[idx + 3];
        }
        v.x += 1; v.y += 1; v.z += 1; v.w += 1;   // self loops
        int tsum = v.x + v.y + v.z + v.w;
        int x = tsum;
        #pragma unroll
        for (int off = 1; off < 32; off <<= 1) {
            int y = __shfl_up_sync(0xFFFFFFFFu, x, off);
            if (lane >= off) x += y;
        }
        if (lane == 31) wsum[wid] = x;
        __syncthreads();
        if (wid == 0) {
            int w = wsum[lane];
            #pragma unroll
            for (int off = 1; off < 32; off <<= 1) {
                int y = __shfl_up_sync(0xFFFFFFFFu, w, off);
                if (lane >= off) w += y;
            }
            wsum[lane] = w;
        }
        __syncthreads();
        int carry = s_carry;
        int excl = carry + (wid > 0 ? wsum[wid - 1] : 0) + x - tsum;
        int e0 = excl;
        int e1 = e0 + v.x;
        int e2 = e1 + v.y;
        int e3 = e2 + v.z;
        if (idx + 3 < N) {
            *(int4*)&rowstart[idx] = make_int4(e0, e1, e2, e3);
            *(int4*)&cursor[idx]   = make_int4(e0, e1, e2, e3);
        } else {
            if (idx + 0 < N) { rowstart[idx + 0] = e0; cursor[idx + 0] = e0; }
            if (idx + 1 < N) { rowstart[idx + 1] = e1; cursor[idx + 1] = e1; }
            if (idx + 2 < N) { rowstart[idx + 2] = e2; cursor[idx + 2] = e2; }
            if (idx + 3 < N) { rowstart[idx + 3] = e3; cursor[idx + 3] = e3; }
        }
        __syncthreads();
        if (tid == 1023) s_carry = carry + wsum[31];
        __syncthreads();
    }
    if (tid == 0) rowstart[N] = s_carry;
}

__global__ void scatter_edges_v(const int* __restrict__ ei, int E, int N,
                                int* __restrict__ cursor,
                                int* __restrict__ sorted_src) {
    int i = blockIdx.x * blockDim.x + threadIdx.x;
    int nv = E >> 2;
    if (i < nv) {
        int4 s4 = *(const int4*)&ei[i * 4];
        int4 d4 = *(const int4*)&ei[E + i * 4];
        int p0 = atomicAdd(&cursor[d4.x], 1);
        int p1 = atomicAdd(&cursor[d4.y], 1);
        int p2 = atomicAdd(&cursor[d4.z], 1);
        int p3 = atomicAdd(&cursor[d4.w], 1);
        sorted_src[p0] = s4.x;
        sorted_src[p1] = s4.y;
        sorted_src[p2] = s4.z;
        sorted_src[p3] = s4.w;
    } else if (i < nv + N) {
        int d = i - nv;                 // self loop
        int p = atomicAdd(&cursor[d], 1);
        sorted_src[p] = d;
    } else {
        int e = nv * 4 + (i - nv - N);  // tail edges
        if (e < E) {
            int s = ei[e], d = ei[E + e];
            int p = atomicAdd(&cursor[d], 1);
            sorted_src[p] = s;
        }
    }
}

// ---------------------------------------------------------------------------
// HGEMM core (variadic macro: commas inside braces are fine).
// Block 128x64, 8 warps (4M x 2N), warp tile 32x32. fp32 acc, fp16 C.
// ---------------------------------------------------------------------------
#define AS_STRIDE 40
#define BS_STRIDE 136

__device__ __forceinline__ void mma16816(float* c, const unsigned int* a,
                                         unsigned int b0, unsigned int b1) {
    asm volatile(
        "mma.sync.aligned.m16n8k16.row.col.f32.f16.f16.f32 "
        "{%0,%1,%2,%3}, {%4,%5,%6,%7}, {%8,%9}, {%0,%1,%2,%3};"
        : "+f"(c[0]), "+f"(c[1]), "+f"(c[2]), "+f"(c[3])
        : "r"(a[0]), "r"(a[1]), "r"(a[2]), "r"(a[3]), "r"(b0), "r"(b1));
}

#define HGEMM_BODY(...)                                                        \
    __shared__ __half As[128 * AS_STRIDE];                                     \
    __shared__ __half Bs[64 * BS_STRIDE];                                      \
    const int tid  = threadIdx.x;                                              \
    const int lane = tid & 31;                                                 \
    const int wid  = tid >> 5;                                                 \
    const int row0 = blockIdx.x * 128;                                         \
    const int col0 = blockIdx.y * 64;                                          \
    const int wm = (wid & 3) * 32;                                             \
    const int wn = (wid >> 2) * 32;                                            \
    {                                                                          \
        int n = tid >> 2;                                                      \
        int p = (tid & 3) * 32;                                                \
        const uint4* src = (const uint4*)&WT[(size_t)(col0 + n) * 128 + p];    \
        uint4* dst = (uint4*)&Bs[n * BS_STRIDE + p];                           \
        dst[0] = src[0]; dst[1] = src[1]; dst[2] = src[2]; dst[3] = src[3];    \
    }                                                                          \
    float acc[2][4][4];                                                        \
    _Pragma("unroll")                                                          \
    for (int mt = 0; mt < 2; mt++)                                             \
        _Pragma("unroll")                                                      \
        for (int nt = 0; nt < 4; nt++)                                         \
            _Pragma("unroll")                                                  \
            for (int q = 0; q < 4; q++) acc[mt][nt][q] = 0.0f;                 \
    const int arow = tid >> 1;                                                 \
    const int acol = (tid & 1) * 16;                                           \
    const int frow = lane >> 2;                                                \
    const int fcol = 2 * (lane & 3);                                           \
    for (int kc = 0; kc < 128; kc += 32) {                                     \
        uint4 v0 = make_uint4(0, 0, 0, 0);                                     \
        uint4 v1 = make_uint4(0, 0, 0, 0);                                     \
        int gr = row0 + arow;                                                  \
        __VA_ARGS__                                                            \
        __syncthreads();                                                       \
        *(uint4*)&As[arow * AS_STRIDE + acol]     = v0;                        \
        *(uint4*)&As[arow * AS_STRIDE + acol + 8] = v1;                        \
        __syncthreads();                                                       \
        _Pragma("unroll")                                                      \
        for (int kk = 0; kk < 32; kk += 16) {                                  \
            unsigned int a[2][4];                                              \
            _Pragma("unroll")                                                  \
            for (int mt = 0; mt < 2; mt++) {                                   \
                int r = wm + mt * 16 + frow;                                   \
                int c = kk + fcol;                                             \
                a[mt][0] = *(const unsigned int*)&As[r * AS_STRIDE + c];       \
                a[mt][1] = *(const unsigned int*)&As[(r + 8) * AS_STRIDE + c]; \
                a[mt][2] = *(const unsigned int*)&As[r * AS_STRIDE + c + 8];   \
                a[mt][3] = *(const unsigned int*)&As[(r + 8) * AS_STRIDE + c + 8]; \
            }                                                                  \
            _Pragma("unroll")                                                  \
            for (int nt = 0; nt < 4; nt++) {                                   \
                int n = wn + nt * 8 + frow;                                    \
                int ck = kc + kk + fcol;                                       \
                unsigned int b0 = *(const unsigned int*)&Bs[n * BS_STRIDE + ck];     \
                unsigned int b1 = *(const unsigned int*)&Bs[n * BS_STRIDE + ck + 8]; \
                mma16816(acc[0][nt], a[0], b0, b1);                            \
                mma16816(acc[1][nt], a[1], b0, b1);                            \
            }                                                                  \
        }                                                                      \
    }                                                                          \
    _Pragma("unroll")                                                          \
    for (int mt = 0; mt < 2; mt++) {                                           \
        int r = row0 + wm + mt * 16 + frow;                                    \
        _Pragma("unroll")                                                      \
        for (int nt = 0; nt < 4; nt++) {                                       \
            int c = col0 + wn + nt * 8 + fcol;                                 \
            if (r < M) {                                                       \
                __half2 h = __floats2half2_rn(acc[mt][nt][0], acc[mt][nt][1]); \
                *(__half2*)&C[(size_t)r * Ncols + c] = h;                      \
            }                                                                  \
            if (r + 8 < M) {                                                   \
                __half2 h = __floats2half2_rn(acc[mt][nt][2], acc[mt][nt][3]); \
                *(__half2*)&C[(size_t)(r + 8) * Ncols + c] = h;                \
            }                                                                  \
        }                                                                      \
    }

// fp16-A variant (layer 2)
__global__ __launch_bounds__(256, 1)
void hgemm_k128(const __half* __restrict__ A, const __half* __restrict__ WT,
                __half* __restrict__ C, int M, int Ncols) {
    HGEMM_BODY(
        if (gr < M) {
            const uint4* s = (const uint4*)&A[(size_t)gr * 128 + kc + acol];
            v0 = s[0]; v1 = s[1];
        }
    )
}

// fp32-A variant (layer 1; converts while staging to smem)
__global__ __launch_bounds__(256, 1)
void hgemm_k128_f32a(const float* __restrict__ A, const __half* __restrict__ WT,
                     __half* __restrict__ C, int M, int Ncols) {
    HGEMM_BODY(
        if (gr < M) {
            const float4* s = (const float4*)&A[(size_t)gr * 128 + kc + acol];
            float4 f0 = s[0];
            float4 f1 = s[1];
            float4 f2 = s[2];
            float4 f3 = s[3];
            __half2 h[8];
            h[0] = __floats2half2_rn(f0.x, f0.y);
            h[1] = __floats2half2_rn(f0.z, f0.w);
            h[2] = __floats2half2_rn(f1.x, f1.y);
            h[3] = __floats2half2_rn(f1.z, f1.w);
            h[4] = __floats2half2_rn(f2.x, f2.y);
            h[5] = __floats2half2_rn(f2.z, f2.w);
            h[6] = __floats2half2_rn(f3.x, f3.y);
            h[7] = __floats2half2_rn(f3.z, f3.w);
            v0 = *(uint4*)&h[0];
            v1 = *(uint4*)&h[4];
        }
    )
}

// ---------------------------------------------------------------------------
// Node attention terms: warp per node, vectorized fp16 loads.
// ---------------------------------------------------------------------------
__global__ __launch_bounds__(256)
void node_alpha1(const __half* __restrict__ h,
                 const float* __restrict__ a_src,
                 const float* __restrict__ a_dst,
                 float* __restrict__ al_s,
                 float* __restrict__ al_d, int N) {
    int w = (blockIdx.x * blockDim.x + threadIdx.x) >> 5;
    int lane = threadIdx.x & 31;
    if (w >= N) return;
    uint2 raw = *(const uint2*)&h[(size_t)w * 128 + lane * 4];
    float2 f0 = __half22float2(*(const __half2*)&raw.x);
    float2 f1 = __half22float2(*(const __half2*)&raw.y);
    float4 asv = *(const float4*)&a_src[lane * 4];
    float4 adv = *(const float4*)&a_dst[lane * 4];
    float ps = f0.x * asv.x + f0.y * asv.y + f1.x * asv.z + f1.y * asv.w;
    float pd = f0.x * adv.x + f0.y * adv.y + f1.x * adv.z + f1.y * adv.w;
    #pragma unroll
    for (int off = 4; off > 0; off >>= 1) {
        ps += __shfl_xor_sync(0xFFFFFFFFu, ps, off);
        pd += __shfl_xor_sync(0xFFFFFFFFu, pd, off);
    }
    if ((lane & 7) == 0) {
        int hd = lane >> 3;
        al_s[w * 4 + hd] = ps;
        al_d[w * 4 + hd] = pd;
    }
}

__global__ __launch_bounds__(256)
void node_alpha2(const __half* __restrict__ h,
                 const float* __restrict__ a_src,
                 const float* __restrict__ a_dst,
                 float* __restrict__ al_s,
                 float* __restrict__ al_d, int N) {
    int w = (blockIdx.x * blockDim.x + threadIdx.x) >> 5;
    int lane = threadIdx.x & 31;
    if (w >= N) return;
    uint4 raw = *(const uint4*)&h[(size_t)w * 256 + lane * 8];
    float2 f0 = __half22float2(*(const __half2*)&raw.x);
    float2 f1 = __half22float2(*(const __half2*)&raw.y);
    float2 f2 = __half22float2(*(const __half2*)&raw.z);
    float2 f3 = __half22float2(*(const __half2*)&raw.w);
    float4 s0 = *(const float4*)&a_src[lane * 8];
    float4 s1 = *(const float4*)&a_src[lane * 8 + 4];
    float4 d0 = *(const float4*)&a_dst[lane * 8];
    float4 d1 = *(const float4*)&a_dst[lane * 8 + 4];
    float ps = f0.x * s0.x + f0.y * s0.y + f1.x * s0.z + f1.y * s0.w
             + f2.x * s1.x + f2.y * s1.y + f3.x * s1.z + f3.y * s1.w;
    float pd = f0.x * d0.x + f0.y * d0.y + f1.x * d0.z + f1.y * d0.w
             + f2.x * d1.x + f2.y * d1.y + f3.x * d1.z + f3.y * d1.w;
    #pragma unroll
    for (int off = 16; off > 0; off >>= 1) {
        ps += __shfl_xor_sync(0xFFFFFFFFu, ps, off);
        pd += __shfl_xor_sync(0xFFFFFFFFu, pd, off);
    }
    if (lane == 0) {
        al_s[w] = ps;
        al_d[w] = pd;
    }
}

// ---------------------------------------------------------------------------
// Layer-1 fused gather, MLP=8, node range [n0, n0+cnt).
// ---------------------------------------------------------------------------
__global__ __launch_bounds__(256)
void gather_agg1(const int* __restrict__ rowstart, const int* __restrict__ ssrc,
                 const float* __restrict__ als, const float* __restrict__ ald,
                 const __half* __restrict__ hlin, const float* __restrict__ bias,
                 __half* __restrict__ outp, int n0, int cnt) {
    int w = (blockIdx.x * blockDim.x + threadIdx.x) >> 5;
    int lane = threadIdx.x & 31;
    if (w >= cnt) return;
    w += n0;
    const int beg = rowstart[w];
    const int end = rowstart[w + 1];
    const int head = lane >> 3;
    const float ad_h = ald[w * 4 + head];

    float ssum = 0.f;
    float4 acc = make_float4(0.f, 0.f, 0.f, 0.f);

    int j = beg;
    for (; j + 8 <= end; j += 8) {
        int sn[8];
        #pragma unroll
        for (int q = 0; q < 8; q++) sn[q] = ssrc[j + q];
        float al[8];
        #pragma unroll
        for (int q = 0; q < 8; q++) al[q] = als[sn[q] * 4 + head];
        uint2 r[8];
        #pragma unroll
        for (int q = 0; q < 8; q++)
            r[q] = *(const uint2*)&hlin[(size_t)sn[q] * 128 + lane * 4];
        #pragma unroll
        for (int q = 0; q < 8; q++) {
            float e = __expf(lrelu(al[q] + ad_h));
            ssum += e;
            float2 a = __half22float2(*(const __half2*)&r[q].x);
            float2 b = __half22float2(*(const __half2*)&r[q].y);
            acc.x = fmaf(e, a.x, acc.x); acc.y = fmaf(e, a.y, acc.y);
            acc.z = fmaf(e, b.x, acc.z); acc.w = fmaf(e, b.y, acc.w);
        }
    }
    for (; j < end; j++) {
        int sn = ssrc[j];
        float e = __expf(lrelu(als[sn * 4 + head] + ad_h));
        uint2 r = *(const uint2*)&hlin[(size_t)sn * 128 + lane * 4];
        ssum += e;
        float2 a = __half22float2(*(const __half2*)&r.x);
        float2 b = __half22float2(*(const __half2*)&r.y);
        acc.x = fmaf(e, a.x, acc.x); acc.y = fmaf(e, a.y, acc.y);
        acc.z = fmaf(e, b.x, acc.z); acc.w = fmaf(e, b.y, acc.w);
    }
    const float inv = 1.0f / (ssum + 1e-16f);
    float4 bb = *(const float4*)&bias[lane * 4];
    acc.x = fmaxf(fmaf(acc.x, inv, bb.x), 0.f);
    acc.y = fmaxf(fmaf(acc.y, inv, bb.y), 0.f);
    acc.z = fmaxf(fmaf(acc.z, inv, bb.z), 0.f);
    acc.w = fmaxf(fmaf(acc.w, inv, bb.w), 0.f);
    __half2 h0 = __floats2half2_rn(acc.x, acc.y);
    __half2 h1 = __floats2half2_rn(acc.z, acc.w);
    uint2 u;
    u.x = *(unsigned int*)&h0;
    u.y = *(unsigned int*)&h1;
    *(uint2*)&outp[(size_t)w * 128 + lane * 4] = u;
}

// ---------------------------------------------------------------------------
// Layer-2 fused gather, MLP=4. fp32 out.
// ---------------------------------------------------------------------------
__global__ __launch_bounds__(256)
void gather_agg2(const int* __restrict__ rowstart, const int* __restrict__ ssrc,
                 const float* __restrict__ als, const float* __restrict__ ald,
                 const __half* __restrict__ hlin, const float* __restrict__ bias,
                 float* __restrict__ outp, int N) {
    int w = (blockIdx.x * blockDim.x + threadIdx.x) >> 5;
    int lane = threadIdx.x & 31;
    if (w >= N) return;
    const int beg = rowstart[w];
    const int end = rowstart[w + 1];
    const float ad = ald[w];

    float ssum = 0.f;
    float4 a0 = make_float4(0.f, 0.f, 0.f, 0.f);
    float4 a1 = make_float4(0.f, 0.f, 0.f, 0.f);

    int j = beg;
    for (; j + 4 <= end; j += 4) {
        int sn0 = ssrc[j], sn1 = ssrc[j + 1], sn2 = ssrc[j + 2], sn3 = ssrc[j + 3];
        float al0 = als[sn0], al1 = als[sn1], al2 = als[sn2], al3 = als[sn3];
        uint4 r0 = *(const uint4*)&hlin[(size_t)sn0 * 256 + lane * 8];
        uint4 r1 = *(const uint4*)&hlin[(size_t)sn1 * 256 + lane * 8];
        uint4 r2 = *(const uint4*)&hlin[(size_t)sn2 * 256 + lane * 8];
        uint4 r3 = *(const uint4*)&hlin[(size_t)sn3 * 256 + lane * 8];
        float e0 = __expf(lrelu(al0 + ad));
        float e1 = __expf(lrelu(al1 + ad));
        float e2 = __expf(lrelu(al2 + ad));
        float e3 = __expf(lrelu(al3 + ad));
        ssum += (e0 + e1) + (e2 + e3);
        #define ACC8(rv, ev)                                                    \
        {                                                                       \
            float2 f0 = __half22float2(*(const __half2*)&rv.x);                 \
            float2 f1 = __half22float2(*(const __half2*)&rv.y);                 \
            float2 f2 = __half22float2(*(const __half2*)&rv.z);                 \
            float2 f3 = __half22float2(*(const __half2*)&rv.w);                 \
            a0.x = fmaf(ev, f0.x, a0.x); a0.y = fmaf(ev, f0.y, a0.y);           \
            a0.z = fmaf(ev, f1.x, a0.z); a0.w = fmaf(ev, f1.y, a0.w);           \
            a1.x = fmaf(ev, f2.x, a1.x); a1.y = fmaf(ev, f2.y, a1.y);           \
            a1.z = fmaf(ev, f3.x, a1.z); a1.w = fmaf(ev, f3.y, a1.w);           \
        }
        ACC8(r0, e0)
        ACC8(r1, e1)
        ACC8(r2, e2)
        ACC8(r3, e3)
    }
    for (; j < end; j++) {
        int sn = ssrc[j];
        float e = __expf(lrelu(als[sn] + ad));
        uint4 r = *(const uint4*)&hlin[(size_t)sn * 256 + lane * 8];
        ssum += e;
        ACC8(r, e)
    }
    #undef ACC8
    const float inv = 1.0f / (ssum + 1e-16f);
    float4 b0 = *(const float4*)&bias[lane * 8];
    float4 b1v = *(const float4*)&bias[lane * 8 + 4];
    a0.x = fmaf(a0.x, inv, b0.x);
    a0.y = fmaf(a0.y, inv, b0.y);
    a0.z = fmaf(a0.z, inv, b0.z);
    a0.w = fmaf(a0.w, inv, b0.w);
    a1.x = fmaf(a1.x, inv, b1v.x);
    a1.y = fmaf(a1.y, inv, b1v.y);
    a1.z = fmaf(a1.z, inv, b1v.z);
    a1.w = fmaf(a1.w, inv, b1v.w);
    float* op = &outp[(size_t)w * 256 + lane * 8];
    *(float4*)&op[0] = a0;
    *(float4*)&op[4] = a1;
}

// ---------------------------------------------------------------------------
// Launch
// ---------------------------------------------------------------------------
extern "C" void kernel_launch(void* const* d_in, const int* in_sizes, int n_in,
                              void* d_out, int out_size) {
    const float* x   = (const float*)d_in[0];
    const int*   ei  = (const int*)d_in[1];
    const float* W1  = (const float*)d_in[2];
    const float* as1 = (const float*)d_in[3];
    const float* ad1 = (const float*)d_in[4];
    const float* b1  = (const float*)d_in[5];
    const float* W2  = (const float*)d_in[6];
    const float* as2 = (const float*)d_in[7];
    const float* ad2 = (const float*)d_in[8];
    const float* b2  = (const float*)d_in[9];
    float* out = (float*)d_out;

    const int N = in_sizes[0] / 128;   // 50000
    const int E = in_sizes[1] / 2;     // 1600000

    float *als1p, *ald1p, *als2p, *ald2p;
    __half *wt1h, *wt2h, *hlin1, *agg1h, *hlin2;
    int *cntp, *rowp, *curp, *ssrcp;
    cudaGetSymbolAddress((void**)&wt1h,  g_wt1h);
    cudaGetSymbolAddress((void**)&wt2h,  g_wt2h);
    cudaGetSymbolAddress((void**)&hlin1, g_hlin1);
    cudaGetSymbolAddress((void**)&als1p, g_als1);
    cudaGetSymbolAddress((void**)&ald1p, g_ald1);
    cudaGetSymbolAddress((void**)&agg1h, g_agg1h);
    cudaGetSymbolAddress((void**)&hlin2, g_hlin2);
    cudaGetSymbolAddress((void**)&als2p, g_als2);
    cudaGetSymbolAddress((void**)&ald2p, g_ald2);
    cudaGetSymbolAddress((void**)&cntp,  g_count);
    cudaGetSymbolAddress((void**)&rowp,  g_rowstart);
    cudaGetSymbolAddress((void**)&curp,  g_cursor);
    cudaGetSymbolAddress((void**)&ssrcp, g_sorted_src);

    static cudaStream_t s2 = nullptr;
    static cudaEvent_t ev_fork = nullptr, ev_csr = nullptr, ev_g1a = nullptr,
                       ev_m2a = nullptr;
    if (s2 == nullptr) {
        cudaStreamCreateWithFlags(&s2, cudaStreamNonBlocking);
        cudaEventCreateWithFlags(&ev_fork, cudaEventDisableTiming);
        cudaEventCreateWithFlags(&ev_csr,  cudaEventDisableTiming);
        cudaEventCreateWithFlags(&ev_g1a,  cudaEventDisableTiming);
        cudaEventCreateWithFlags(&ev_m2a,  cudaEventDisableTiming);
    }

    const int NW_BLOCKS = (N * 32 + 255) / 256;
    const int Nh = (N / 2 + 127) & ~127;      // chunk0 size, multiple of 128
    const int Nh2 = N - Nh;
    const int HIST_THREADS = (E >> 2) + (E & 3);
    const int SCAT_THREADS = (E >> 2) + N + (E & 3);

    // --- fork: CSR build on s2 ---
    cudaEventRecord(ev_fork, 0);
    cudaStreamWaitEvent(s2, ev_fork, 0);
    cudaMemsetAsync(cntp, 0, (size_t)N * sizeof(int), s2);
    hist_dst_v<<<(HIST_THREADS + 255) / 256, 256, 0, s2>>>(ei, E, cntp);
    scan_counts<<<1, 1024, 0, s2>>>(cntp, rowp, curp, N);
    scatter_edges_v<<<(SCAT_THREADS + 255) / 256, 256, 0, s2>>>(ei, E, N, curp, ssrcp);
    cudaEventRecord(ev_csr, s2);

    // --- main: weights cvt + GEMM1 (fp32 A) + alpha1 ---
    cvt_wts<<<(128 * 128 + 256 * 128 + 255) / 256, 256>>>(W1, wt1h, W2, wt2h);
    {
        dim3 grid((N + 127) / 128, 2);
        hgemm_k128_f32a<<<grid, 256>>>(x, wt1h, hlin1, N, 128);
    }
    node_alpha1<<<NW_BLOCKS, 256>>>(hlin1, as1, ad1, als1p, ald1p, N);

    // --- join CSR; gather1 in two chunks ---
    cudaStreamWaitEvent(0, ev_csr, 0);
    gather_agg1<<<(Nh * 32 + 255) / 256, 256>>>(rowp, ssrcp, als1p, ald1p,
                                                hlin1, b1, agg1h, 0, Nh);
    cudaEventRecord(ev_g1a, 0);
    gather_agg1<<<(Nh2 * 32 + 255) / 256, 256>>>(rowp, ssrcp, als1p, ald1p,
                                                 hlin1, b1, agg1h, Nh, Nh2);

    // --- GEMM2 chunk0 on s2 (overlaps gather1 chunk1) ---
    cudaStreamWaitEvent(s2, ev_g1a, 0);
    {
        dim3 grid(Nh / 128, 4);
        hgemm_k128<<<grid, 256, 0, s2>>>(agg1h, wt2h, hlin2, Nh, 256);
    }
    cudaEventRecord(ev_m2a, s2);

    // --- GEMM2 chunk1 on main ---
    {
        dim3 grid((Nh2 + 127) / 128, 4);
        hgemm_k128<<<grid, 256>>>(agg1h + (size_t)Nh * 128, wt2h,
                                  hlin2 + (size_t)Nh * 256, Nh2, 256);
    }
    cudaStreamWaitEvent(0, ev_m2a, 0);

    // --- alpha2 + gather2 ---
    node_alpha2<<<NW_BLOCKS, 256>>>(hlin2, as2, ad2, als2p, ald2p, N);
    gather_agg2<<<NW_BLOCKS, 256>>>(rowp, ssrcp, als2p, ald2p, hlin2, b2, out, N);
}

// round 10
// speedup vs baseline: 1.0091x; 1.0091x over previous
#include <cuda_runtime.h>
#include <cuda_fp16.h>

// ---------------------------------------------------------------------------
// GAT encoder: 2x GATConv (4 heads x 32, then 1 head x 256), ReLU between.
// R9: R6 single-kernel main chain + R7's verified wins (vectorized CSR build,
//     fused weight cvt, fp32-A GEMM1). Chunked gather1/GEMM2 overlap REVERTED
//     (bandwidth-bound kernels don't overlap; split grids double the
//     degree-imbalance tail).
// ---------------------------------------------------------------------------

#define NNODES 50000
#define EMAX   1700000   // >= E + N

__device__ __align__(16) __half g_wt1h[128 * 128];
__device__ __align__(16) __half g_wt2h[256 * 128];
__device__ __align__(16) __half g_hlin1[NNODES * 128];
__device__ __align__(16) float  g_als1[NNODES * 4];
__device__ __align__(16) float  g_ald1[NNODES * 4];
__device__ __align__(16) __half g_agg1h[NNODES * 128];
__device__ __align__(16) __half g_hlin2[NNODES * 256];
__device__ __align__(16) float  g_als2[NNODES];
__device__ __align__(16) float  g_ald2[NNODES];
__device__ int g_count[NNODES];
__device__ int g_rowstart[NNODES + 1];
__device__ int g_cursor[NNODES];
__device__ int g_sorted_src[EMAX];

__device__ __forceinline__ float lrelu(float x) {
    return x > 0.0f ? x : 0.2f * x;
}

// ---------------------------------------------------------------------------
// Weight conversion (both layers in one launch)
// ---------------------------------------------------------------------------
__global__ void cvt_wts(const float* __restrict__ W1, __half* __restrict__ WT1,
                        const float* __restrict__ W2, __half* __restrict__ WT2) {
    int i = blockIdx.x * blockDim.x + threadIdx.x;
    if (i < 128 * 128) {
        int n = i >> 7, k = i & 127;
        WT1[i] = __float2half(W1[k * 128 + n]);
    } else if (i < 128 * 128 + 256 * 128) {
        int j = i - 128 * 128;
        int n = j >> 7, k = j & 127;
        WT2[j] = __float2half(W2[k * 256 + n]);
    }
}

// ---------------------------------------------------------------------------
// CSR build (vectorized). Self-loops handled as +1 per node inside the scan.
// ---------------------------------------------------------------------------
__global__ void hist_dst_v(const int* __restrict__ ei, int E,
                           int* __restrict__ cnt) {
    int i = blockIdx.x * blockDim.x + threadIdx.x;
    int nv = E >> 2;
    if (i < nv) {
        int4 d4 = *(const int4*)&ei[E + i * 4];
        atomicAdd(&cnt[d4.x], 1);
        atomicAdd(&cnt[d4.y], 1);
        atomicAdd(&cnt[d4.z], 1);
        atomicAdd(&cnt[d4.w], 1);
    } else {
        int e = nv * 4 + (i - nv);      // tail edges (E not multiple of 4)
        if (e < E) atomicAdd(&cnt[ei[E + e]], 1);
    }
}

// exclusive scan of (cnt[i] + 1)  -- the +1 is each node's self loop.
__global__ __launch_bounds__(1024, 1)
void scan_counts(const int* __restrict__ cnt, int* __restrict__ rowstart,
                 int* __restrict__ cursor, int N) {
    __shared__ int wsum[32];
    __shared__ int s_carry;
    const int tid = threadIdx.x, lane = tid & 31, wid = tid >> 5;
    if (tid == 0) s_carry = 0;
    __syncthreads();
    for (int base = 0; base < N; base += 4096) {
        int idx = base + tid * 4;
        int4 v = make_int4(-1, -1, -1, -1);   // -1 + 1 = 0 for out-of-range
        if (idx + 3 < N) v = *(const int4*)&cnt[idx];
        else {
            if (idx + 0 < N) v.x = cnt[idx + 0];
            if (idx + 1 < N) v.y = cnt[idx + 1];
            if (idx + 2 < N) v.z = cnt[idx + 2];
            if (idx + 3 < N) v.w = cnt[idx + 3];
        }
        v.x += 1; v.y += 1; v.z += 1; v.w += 1;   // self loops
        int tsum = v.x + v.y + v.z + v.w;
        int x = tsum;
        #pragma unroll
        for (int off = 1; off < 32; off <<= 1) {
            int y = __shfl_up_sync(0xFFFFFFFFu, x, off);
            if (lane >= off) x += y;
        }
        if (lane == 31) wsum[wid] = x;
        __syncthreads();
        if (wid == 0) {
            int w = wsum[lane];
            #pragma unroll
            for (int off = 1; off < 32; off <<= 1) {
                int y = __shfl_up_sync(0xFFFFFFFFu, w, off);
                if (lane >= off) w += y;
            }
            wsum[lane] = w;
        }
        __syncthreads();
        int carry = s_carry;
        int excl = carry + (wid > 0 ? wsum[wid - 1] : 0) + x - tsum;
        int e0 = excl;
        int e1 = e0 + v.x;
        int e2 = e1 + v.y;
        int e3 = e2 + v.z;
        if (idx + 3 < N) {
            *(int4*)&rowstart[idx] = make_int4(e0, e1, e2, e3);
            *(int4*)&cursor[idx]   = make_int4(e0, e1, e2, e3);
        } else {
            if (idx + 0 < N) { rowstart[idx + 0] = e0; cursor[idx + 0] = e0; }
            if (idx + 1 < N) { rowstart[idx + 1] = e1; cursor[idx + 1] = e1; }
            if (idx + 2 < N) { rowstart[idx + 2] = e2; cursor[idx + 2] = e2; }
            if (idx + 3 < N) { rowstart[idx + 3] = e3; cursor[idx + 3] = e3; }
        }
        __syncthreads();
        if (tid == 1023) s_carry = carry + wsum[31];
        __syncthreads();
    }
    if (tid == 0) rowstart[N] = s_carry;
}

__global__ void scatter_edges_v(const int* __restrict__ ei, int E, int N,
                                int* __restrict__ cursor,
                                int* __restrict__ sorted_src) {
    int i = blockIdx.x * blockDim.x + threadIdx.x;
    int nv = E >> 2;
    if (i < nv) {
        int4 s4 = *(const int4*)&ei[i * 4];
        int4 d4 = *(const int4*)&ei[E + i * 4];
        int p0 = atomicAdd(&cursor[d4.x], 1);
        int p1 = atomicAdd(&cursor[d4.y], 1);
        int p2 = atomicAdd(&cursor[d4.z], 1);
        int p3 = atomicAdd(&cursor[d4.w], 1);
        sorted_src[p0] = s4.x;
        sorted_src[p1] = s4.y;
        sorted_src[p2] = s4.z;
        sorted_src[p3] = s4.w;
    } else if (i < nv + N) {
        int d = i - nv;                 // self loop
        int p = atomicAdd(&cursor[d], 1);
        sorted_src[p] = d;
    } else {
        int e = nv * 4 + (i - nv - N);  // tail edges
        if (e < E) {
            int s = ei[e], d = ei[E + e];
            int p = atomicAdd(&cursor[d], 1);
            sorted_src[p] = s;
        }
    }
}

// ---------------------------------------------------------------------------
// HGEMM core (variadic macro). Block 128x64, 8 warps (4M x 2N), 32x32 warp
// tile. fp32 acc, fp16 C.
// ---------------------------------------------------------------------------
#define AS_STRIDE 40
#define BS_STRIDE 136

__device__ __forceinline__ void mma16816(float* c, const unsigned int* a,
                                         unsigned int b0, unsigned int b1) {
    asm volatile(
        "mma.sync.aligned.m16n8k16.row.col.f32.f16.f16.f32 "
        "{%0,%1,%2,%3}, {%4,%5,%6,%7}, {%8,%9}, {%0,%1,%2,%3};"
        : "+f"(c[0]), "+f"(c[1]), "+f"(c[2]), "+f"(c[3])
        : "r"(a[0]), "r"(a[1]), "r"(a[2]), "r"(a[3]), "r"(b0), "r"(b1));
}

#define HGEMM_BODY(...)                                                        \
    __shared__ __half As[128 * AS_STRIDE];                                     \
    __shared__ __half Bs[64 * BS_STRIDE];                                      \
    const int tid  = threadIdx.x;                                              \
    const int lane = tid & 31;                                                 \
    const int wid  = tid >> 5;                                                 \
    const int row0 = blockIdx.x * 128;                                         \
    const int col0 = blockIdx.y * 64;                                          \
    const int wm = (wid & 3) * 32;                                             \
    const int wn = (wid >> 2) * 32;                                            \
    {                                                                          \
        int n = tid >> 2;                                                      \
        int p = (tid & 3) * 32;                                                \
        const uint4* src = (const uint4*)&WT[(size_t)(col0 + n) * 128 + p];    \
        uint4* dst = (uint4*)&Bs[n * BS_STRIDE + p];                           \
        dst[0] = src[0]; dst[1] = src[1]; dst[2] = src[2]; dst[3] = src[3];    \
    }                                                                          \
    float acc[2][4][4];                                                        \
    _Pragma("unroll")                                                          \
    for (int mt = 0; mt < 2; mt++)                                             \
        _Pragma("unroll")                                                      \
        for (int nt = 0; nt < 4; nt++)                                         \
            _Pragma("unroll")                                                  \
            for (int q = 0; q < 4; q++) acc[mt][nt][q] = 0.0f;                 \
    const int arow = tid >> 1;                                                 \
    const int acol = (tid & 1) * 16;                                           \
    const int frow = lane >> 2;                                                \
    const int fcol = 2 * (lane & 3);                                           \
    for (int kc = 0; kc < 128; kc += 32) {                                     \
        uint4 v0 = make_uint4(0, 0, 0, 0);                                     \
        uint4 v1 = make_uint4(0, 0, 0, 0);                                     \
        int gr = row0 + arow;                                                  \
        __VA_ARGS__                                                            \
        __syncthreads();                                                       \
        *(uint4*)&As[arow * AS_STRIDE + acol]     = v0;                        \
        *(uint4*)&As[arow * AS_STRIDE + acol + 8] = v1;                        \
        __syncthreads();                                                       \
        _Pragma("unroll")                                                      \
        for (int kk = 0; kk < 32; kk += 16) {                                  \
            unsigned int a[2][4];                                              \
            _Pragma("unroll")                                                  \
            for (int mt = 0; mt < 2; mt++) {                                   \
                int r = wm + mt * 16 + frow;                                   \
                int c = kk + fcol;                                             \
                a[mt][0] = *(const unsigned int*)&As[r * AS_STRIDE + c];       \
                a[mt][1] = *(const unsigned int*)&As[(r + 8) * AS_STRIDE + c]; \
                a[mt][2] = *(const unsigned int*)&As[r * AS_STRIDE + c + 8];   \
                a[mt][3] = *(const unsigned int*)&As[(r + 8) * AS_STRIDE + c + 8]; \
            }                                                                  \
            _Pragma("unroll")                                                  \
            for (int nt = 0; nt < 4; nt++) {                                   \
                int n = wn + nt * 8 + frow;                                    \
                int ck = kc + kk + fcol;                                       \
                unsigned int b0 = *(const unsigned int*)&Bs[n * BS_STRIDE + ck];     \
                unsigned int b1 = *(const unsigned int*)&Bs[n * BS_STRIDE + ck + 8]; \
                mma16816(acc[0][nt], a[0], b0, b1);                            \
                mma16816(acc[1][nt], a[1], b0, b1);                            \
            }                                                                  \
        }                                                                      \
    }                                                                          \
    _Pragma("unroll")                                                          \
    for (int mt = 0; mt < 2; mt++) {                                           \
        int r = row0 + wm + mt * 16 + frow;                                    \
        _Pragma("unroll")                                                      \
        for (int nt = 0; nt < 4; nt++) {                                       \
            int c = col0 + wn + nt * 8 + fcol;                                 \
            if (r < M) {                                                       \
                __half2 h = __floats2half2_rn(acc[mt][nt][0], acc[mt][nt][1]); \
                *(__half2*)&C[(size_t)r * Ncols + c] = h;                      \
            }                                                                  \
            if (r + 8 < M) {                                                   \
                __half2 h = __floats2half2_rn(acc[mt][nt][2], acc[mt][nt][3]); \
                *(__half2*)&C[(size_t)(r + 8) * Ncols + c] = h;                \
            }                                                                  \
        }                                                                      \
    }

// fp16-A variant (layer 2)
__global__ __launch_bounds__(256, 1)
void hgemm_k128(const __half* __restrict__ A, const __half* __restrict__ WT,
                __half* __restrict__ C, int M, int Ncols) {
    HGEMM_BODY(
        if (gr < M) {
            const uint4* s = (const uint4*)&A[(size_t)gr * 128 + kc + acol];
            v0 = s[0]; v1 = s[1];
        }
    )
}

// fp32-A variant (layer 1; converts while staging to smem)
__global__ __launch_bounds__(256, 1)
void hgemm_k128_f32a(const float* __restrict__ A, const __half* __restrict__ WT,
                     __half* __restrict__ C, int M, int Ncols) {
    HGEMM_BODY(
        if (gr < M) {
            const float4* s = (const float4*)&A[(size_t)gr * 128 + kc + acol];
            float4 f0 = s[0];
            float4 f1 = s[1];
            float4 f2 = s[2];
            float4 f3 = s[3];
            __half2 h[8];
            h[0] = __floats2half2_rn(f0.x, f0.y);
            h[1] = __floats2half2_rn(f0.z, f0.w);
            h[2] = __floats2half2_rn(f1.x, f1.y);
            h[3] = __floats2half2_rn(f1.z, f1.w);
            h[4] = __floats2half2_rn(f2.x, f2.y);
            h[5] = __floats2half2_rn(f2.z, f2.w);
            h[6] = __floats2half2_rn(f3.x, f3.y);
            h[7] = __floats2half2_rn(f3.z, f3.w);
            v0 = *(uint4*)&h[0];
            v1 = *(uint4*)&h[4];
        }
    )
}

// ---------------------------------------------------------------------------
// Node attention terms: warp per node, vectorized fp16 loads.
// ---------------------------------------------------------------------------
__global__ __launch_bounds__(256)
void node_alpha1(const __half* __restrict__ h,
                 const float* __restrict__ a_src,
                 const float* __restrict__ a_dst,
                 float* __restrict__ al_s,
                 float* __restrict__ al_d, int N) {
    int w = (blockIdx.x * blockDim.x + threadIdx.x) >> 5;
    int lane = threadIdx.x & 31;
    if (w >= N) return;
    uint2 raw = *(const uint2*)&h[(size_t)w * 128 + lane * 4];
    float2 f0 = __half22float2(*(const __half2*)&raw.x);
    float2 f1 = __half22float2(*(const __half2*)&raw.y);
    float4 asv = *(const float4*)&a_src[lane * 4];
    float4 adv = *(const float4*)&a_dst[lane * 4];
    float ps = f0.x * asv.x + f0.y * asv.y + f1.x * asv.z + f1.y * asv.w;
    float pd = f0.x * adv.x + f0.y * adv.y + f1.x * adv.z + f1.y * adv.w;
    #pragma unroll
    for (int off = 4; off > 0; off >>= 1) {
        ps += __shfl_xor_sync(0xFFFFFFFFu, ps, off);
        pd += __shfl_xor_sync(0xFFFFFFFFu, pd, off);
    }
    if ((lane & 7) == 0) {
        int hd = lane >> 3;
        al_s[w * 4 + hd] = ps;
        al_d[w * 4 + hd] = pd;
    }
}

__global__ __launch_bounds__(256)
void node_alpha2(const __half* __restrict__ h,
                 const float* __restrict__ a_src,
                 const float* __restrict__ a_dst,
                 float* __restrict__ al_s,
                 float* __restrict__ al_d, int N) {
    int w = (blockIdx.x * blockDim.x + threadIdx.x) >> 5;
    int lane = threadIdx.x & 31;
    if (w >= N) return;
    uint4 raw = *(const uint4*)&h[(size_t)w * 256 + lane * 8];
    float2 f0 = __half22float2(*(const __half2*)&raw.x);
    float2 f1 = __half22float2(*(const __half2*)&raw.y);
    float2 f2 = __half22float2(*(const __half2*)&raw.z);
    float2 f3 = __half22float2(*(const __half2*)&raw.w);
    float4 s0 = *(const float4*)&a_src[lane * 8];
    float4 s1 = *(const float4*)&a_src[lane * 8 + 4];
    float4 d0 = *(const float4*)&a_dst[lane * 8];
    float4 d1 = *(const float4*)&a_dst[lane * 8 + 4];
    float ps = f0.x * s0.x + f0.y * s0.y + f1.x * s0.z + f1.y * s0.w
             + f2.x * s1.x + f2.y * s1.y + f3.x * s1.z + f3.y * s1.w;
    float pd = f0.x * d0.x + f0.y * d0.y + f1.x * d0.z + f1.y * d0.w
             + f2.x * d1.x + f2.y * d1.y + f3.x * d1.z + f3.y * d1.w;
    #pragma unroll
    for (int off = 16; off > 0; off >>= 1) {
        ps += __shfl_xor_sync(0xFFFFFFFFu, ps, off);
        pd += __shfl_xor_sync(0xFFFFFFFFu, pd, off);
    }
    if (lane == 0) {
        al_s[w] = ps;
        al_d[w] = pd;
    }
}

// ---------------------------------------------------------------------------
// Layer-1 fused gather, MLP=8. out = (sum e*v)/(sum e + 1e-16), bias + relu.
// ---------------------------------------------------------------------------
__global__ __launch_bounds__(256)
void gather_agg1(const int* __restrict__ rowstart, const int* __restrict__ ssrc,
                 const float* __restrict__ als, const float* __restrict__ ald,
                 const __half* __restrict__ hlin, const float* __restrict__ bias,
                 __half* __restrict__ outp, int N) {
    int w = (blockIdx.x * blockDim.x + threadIdx.x) >> 5;
    int lane = threadIdx.x & 31;
    if (w >= N) return;
    const int beg = rowstart[w];
    const int end = rowstart[w + 1];
    const int head = lane >> 3;
    const float ad_h = ald[w * 4 + head];

    float ssum = 0.f;
    float4 acc = make_float4(0.f, 0.f, 0.f, 0.f);

    int j = beg;
    for (; j + 8 <= end; j += 8) {
        int sn[8];
        #pragma unroll
        for (int q = 0; q < 8; q++) sn[q] = ssrc[j + q];
        float al[8];
        #pragma unroll
        for (int q = 0; q < 8; q++) al[q] = als[sn[q] * 4 + head];
        uint2 r[8];
        #pragma unroll
        for (int q = 0; q < 8; q++)
            r[q] = *(const uint2*)&hlin[(size_t)sn[q] * 128 + lane * 4];
        #pragma unroll
        for (int q = 0; q < 8; q++) {
            float e = __expf(lrelu(al[q] + ad_h));
            ssum += e;
            float2 a = __half22float2(*(const __half2*)&r[q].x);
            float2 b = __half22float2(*(const __half2*)&r[q].y);
            acc.x = fmaf(e, a.x, acc.x); acc.y = fmaf(e, a.y, acc.y);
            acc.z = fmaf(e, b.x, acc.z); acc.w = fmaf(e, b.y, acc.w);
        }
    }
    for (; j < end; j++) {
        int sn = ssrc[j];
        float e = __expf(lrelu(als[sn * 4 + head] + ad_h));
        uint2 r = *(const uint2*)&hlin[(size_t)sn * 128 + lane * 4];
        ssum += e;
        float2 a = __half22float2(*(const __half2*)&r.x);
        float2 b = __half22float2(*(const __half2*)&r.y);
        acc.x = fmaf(e, a.x, acc.x); acc.y = fmaf(e, a.y, acc.y);
        acc.z = fmaf(e, b.x, acc.z); acc.w = fmaf(e, b.y, acc.w);
    }
    const float inv = 1.0f / (ssum + 1e-16f);
    float4 bb = *(const float4*)&bias[lane * 4];
    acc.x = fmaxf(fmaf(acc.x, inv, bb.x), 0.f);
    acc.y = fmaxf(fmaf(acc.y, inv, bb.y), 0.f);
    acc.z = fmaxf(fmaf(acc.z, inv, bb.z), 0.f);
    acc.w = fmaxf(fmaf(acc.w, inv, bb.w), 0.f);
    __half2 h0 = __floats2half2_rn(acc.x, acc.y);
    __half2 h1 = __floats2half2_rn(acc.z, acc.w);
    uint2 u;
    u.x = *(unsigned int*)&h0;
    u.y = *(unsigned int*)&h1;
    *(uint2*)&outp[(size_t)w * 128 + lane * 4] = u;
}

// ---------------------------------------------------------------------------
// Layer-2 fused gather, MLP=4. fp32 out.
// ---------------------------------------------------------------------------
__global__ __launch_bounds__(256)
void gather_agg2(const int* __restrict__ rowstart, const int* __restrict__ ssrc,
                 const float* __restrict__ als, const float* __restrict__ ald,
                 const __half* __restrict__ hlin, const float* __restrict__ bias,
                 float* __restrict__ outp, int N) {
    int w = (blockIdx.x * blockDim.x + threadIdx.x) >> 5;
    int lane = threadIdx.x & 31;
    if (w >= N) return;
    const int beg = rowstart[w];
    const int end = rowstart[w + 1];
    const float ad = ald[w];

    float ssum = 0.f;
    float4 a0 = make_float4(0.f, 0.f, 0.f, 0.f);
    float4 a1 = make_float4(0.f, 0.f, 0.f, 0.f);

    int j = beg;
    for (; j + 4 <= end; j += 4) {
        int sn0 = ssrc[j], sn1 = ssrc[j + 1], sn2 = ssrc[j + 2], sn3 = ssrc[j + 3];
        float al0 = als[sn0], al1 = als[sn1], al2 = als[sn2], al3 = als[sn3];
        uint4 r0 = *(const uint4*)&hlin[(size_t)sn0 * 256 + lane * 8];
        uint4 r1 = *(const uint4*)&hlin[(size_t)sn1 * 256 + lane * 8];
        uint4 r2 = *(const uint4*)&hlin[(size_t)sn2 * 256 + lane * 8];
        uint4 r3 = *(const uint4*)&hlin[(size_t)sn3 * 256 + lane * 8];
        float e0 = __expf(lrelu(al0 + ad));
        float e1 = __expf(lrelu(al1 + ad));
        float e2 = __expf(lrelu(al2 + ad));
        float e3 = __expf(lrelu(al3 + ad));
        ssum += (e0 + e1) + (e2 + e3);
        #define ACC8(rv, ev)                                                    \
        {                                                                       \
            float2 f0 = __half22float2(*(const __half2*)&rv.x);                 \
            float2 f1 = __half22float2(*(const __half2*)&rv.y);                 \
            float2 f2 = __half22float2(*(const __half2*)&rv.z);                 \
            float2 f3 = __half22float2(*(const __half2*)&rv.w);                 \
            a0.x = fmaf(ev, f0.x, a0.x); a0.y = fmaf(ev, f0.y, a0.y);           \
            a0.z = fmaf(ev, f1.x, a0.z); a0.w = fmaf(ev, f1.y, a0.w);           \
            a1.x = fmaf(ev, f2.x, a1.x); a1.y = fmaf(ev, f2.y, a1.y);           \
            a1.z = fmaf(ev, f3.x, a1.z); a1.w = fmaf(ev, f3.y, a1.w);           \
        }
        ACC8(r0, e0)
        ACC8(r1, e1)
        ACC8(r2, e2)
        ACC8(r3, e3)
    }
    for (; j < end; j++) {
        int sn = ssrc[j];
        float e = __expf(lrelu(als[sn] + ad));
        uint4 r = *(const uint4*)&hlin[(size_t)sn * 256 + lane * 8];
        ssum += e;
        ACC8(r, e)
    }
    #undef ACC8
    const float inv = 1.0f / (ssum + 1e-16f);
    float4 b0 = *(const float4*)&bias[lane * 8];
    float4 b1v = *(const float4*)&bias[lane * 8 + 4];
    a0.x = fmaf(a0.x, inv, b0.x);
    a0.y = fmaf(a0.y, inv, b0.y);
    a0.z = fmaf(a0.z, inv, b0.z);
    a0.w = fmaf(a0.w, inv, b0.w);
    a1.x = fmaf(a1.x, inv, b1v.x);
    a1.y = fmaf(a1.y, inv, b1v.y);
    a1.z = fmaf(a1.z, inv, b1v.z);
    a1.w = fmaf(a1.w, inv, b1v.w);
    float* op = &outp[(size_t)w * 256 + lane * 8];
    *(float4*)&op[0] = a0;
    *(float4*)&op[4] = a1;
}

// ---------------------------------------------------------------------------
// Launch
// ---------------------------------------------------------------------------
extern "C" void kernel_launch(void* const* d_in, const int* in_sizes, int n_in,
                              void* d_out, int out_size) {
    const float* x   = (const float*)d_in[0];
    const int*   ei  = (const int*)d_in[1];
    const float* W1  = (const float*)d_in[2];
    const float* as1 = (const float*)d_in[3];
    const float* ad1 = (const float*)d_in[4];
    const float* b1  = (const float*)d_in[5];
    const float* W2  = (const float*)d_in[6];
    const float* as2 = (const float*)d_in[7];
    const float* ad2 = (const float*)d_in[8];
    const float* b2  = (const float*)d_in[9];
    float* out = (float*)d_out;

    const int N = in_sizes[0] / 128;   // 50000
    const int E = in_sizes[1] / 2;     // 1600000

    float *als1p, *ald1p, *als2p, *ald2p;
    __half *wt1h, *wt2h, *hlin1, *agg1h, *hlin2;
    int *cntp, *rowp, *curp, *ssrcp;
    cudaGetSymbolAddress((void**)&wt1h,  g_wt1h);
    cudaGetSymbolAddress((void**)&wt2h,  g_wt2h);
    cudaGetSymbolAddress((void**)&hlin1, g_hlin1);
    cudaGetSymbolAddress((void**)&als1p, g_als1);
    cudaGetSymbolAddress((void**)&ald1p, g_ald1);
    cudaGetSymbolAddress((void**)&agg1h, g_agg1h);
    cudaGetSymbolAddress((void**)&hlin2, g_hlin2);
    cudaGetSymbolAddress((void**)&als2p, g_als2);
    cudaGetSymbolAddress((void**)&ald2p, g_ald2);
    cudaGetSymbolAddress((void**)&cntp,  g_count);
    cudaGetSymbolAddress((void**)&rowp,  g_rowstart);
    cudaGetSymbolAddress((void**)&curp,  g_cursor);
    cudaGetSymbolAddress((void**)&ssrcp, g_sorted_src);

    static cudaStream_t s2 = nullptr;
    static cudaEvent_t ev_fork = nullptr, ev_csr = nullptr;
    if (s2 == nullptr) {
        cudaStreamCreateWithFlags(&s2, cudaStreamNonBlocking);
        cudaEventCreateWithFlags(&ev_fork, cudaEventDisableTiming);
        cudaEventCreateWithFlags(&ev_csr,  cudaEventDisableTiming);
    }

    const int NW_BLOCKS = (N * 32 + 255) / 256;
    const int HIST_THREADS = (E >> 2) + (E & 3);
    const int SCAT_THREADS = (E >> 2) + N + (E & 3);

    // --- fork: CSR build on s2 (atomic/int work; disjoint from GEMM chain) ---
    cudaEventRecord(ev_fork, 0);
    cudaStreamWaitEvent(s2, ev_fork, 0);
    cudaMemsetAsync(cntp, 0, (size_t)N * sizeof(int), s2);
    hist_dst_v<<<(HIST_THREADS + 255) / 256, 256, 0, s2>>>(ei, E, cntp);
    scan_counts<<<1, 1024, 0, s2>>>(cntp, rowp, curp, N);
    scatter_edges_v<<<(SCAT_THREADS + 255) / 256, 256, 0, s2>>>(ei, E, N, curp, ssrcp);
    cudaEventRecord(ev_csr, s2);

    // --- main: weights cvt + GEMM1 (fp32 A) + alpha1 ---
    cvt_wts<<<(128 * 128 + 256 * 128 + 255) / 256, 256>>>(W1, wt1h, W2, wt2h);
    {
        dim3 grid((N + 127) / 128, 2);
        hgemm_k128_f32a<<<grid, 256>>>(x, wt1h, hlin1, N, 128);
    }
    node_alpha1<<<NW_BLOCKS, 256>>>(hlin1, as1, ad1, als1p, ald1p, N);

    // --- join CSR; single-kernel gather1 ---
    cudaStreamWaitEvent(0, ev_csr, 0);
    gather_agg1<<<NW_BLOCKS, 256>>>(rowp, ssrcp, als1p, ald1p, hlin1, b1, agg1h, N);

    // --- layer 2 (single GEMM) ---
    {
        dim3 grid((N + 127) / 128, 4);
        hgemm_k128<<<grid, 256>>>(agg1h, wt2h, hlin2, N, 256);
    }
    node_alpha2<<<NW_BLOCKS, 256>>>(hlin2, as2, ad2, als2p, ald2p, N);
    gather_agg2<<<NW_BLOCKS, 256>>>(rowp, ssrcp, als2p, ald2p, hlin2, b2, out, N);
}

// round 12
// speedup vs baseline: 1.0211x; 1.0119x over previous
#include <cuda_runtime.h>
#include <cuda_fp16.h>

// ---------------------------------------------------------------------------
// GAT encoder: 2x GATConv (4 heads x 32, then 1 head x 256), ReLU between.
// R11 (= R10 resubmit; prior run hit transient "device busy" infra failure):
//      exact R6 main chain (verified 241.6us: separate cvt_f2h, fp16-A HMMA
//      GEMMs, gather1 MLP=4, gather2 MLP=4) + ONLY the vectorized CSR build
//      (int4 edge loads, self-loops folded into scan) on stream s2.
// ---------------------------------------------------------------------------

#define NNODES 50000
#define EMAX   1700000   // >= E + N

__device__ __align__(16) __half g_xh[NNODES * 128];
__device__ __align__(16) __half g_wt1h[128 * 128];
__device__ __align__(16) __half g_wt2h[256 * 128];
__device__ __align__(16) __half g_hlin1[NNODES * 128];
__device__ __align__(16) float  g_als1[NNODES * 4];
__device__ __align__(16) float  g_ald1[NNODES * 4];
__device__ __align__(16) __half g_agg1h[NNODES * 128];
__device__ __align__(16) __half g_hlin2[NNODES * 256];
__device__ __align__(16) float  g_als2[NNODES];
__device__ __align__(16) float  g_ald2[NNODES];
__device__ int g_count[NNODES];
__device__ int g_rowstart[NNODES + 1];
__device__ int g_cursor[NNODES];
__device__ int g_sorted_src[EMAX];

__device__ __forceinline__ float lrelu(float x) {
    return x > 0.0f ? x : 0.2f * x;
}

// ---------------------------------------------------------------------------
// Conversions (R6-style: x converted standalone; weights fused pair)
// ---------------------------------------------------------------------------
__global__ void cvt_f2h(const float* __restrict__ in, __half* __restrict__ out, int n4) {
    int i = blockIdx.x * blockDim.x + threadIdx.x;
    if (i >= n4) return;
    float4 v = *(const float4*)&in[i * 4];
    __half2 h0 = __floats2half2_rn(v.x, v.y);
    __half2 h1 = __floats2half2_rn(v.z, v.w);
    uint2 u;
    u.x = *(unsigned int*)&h0;
    u.y = *(unsigned int*)&h1;
    *(uint2*)&out[i * 4] = u;
}

__global__ void cvt_wts(const float* __restrict__ W1, __half* __restrict__ WT1,
                        const float* __restrict__ W2, __half* __restrict__ WT2) {
    int i = blockIdx.x * blockDim.x + threadIdx.x;
    if (i < 128 * 128) {
        int n = i >> 7, k = i & 127;
        WT1[i] = __float2half(W1[k * 128 + n]);
    } else if (i < 128 * 128 + 256 * 128) {
        int j = i - 128 * 128;
        int n = j >> 7, k = j & 127;
        WT2[j] = __float2half(W2[k * 256 + n]);
    }
}

// ---------------------------------------------------------------------------
// CSR build (vectorized; self-loops folded into the scan as +1 per node).
// ---------------------------------------------------------------------------
__global__ void hist_dst_v(const int* __restrict__ ei, int E,
                           int* __restrict__ cnt) {
    int i = blockIdx.x * blockDim.x + threadIdx.x;
    int nv = E >> 2;
    if (i < nv) {
        int4 d4 = *(const int4*)&ei[E + i * 4];
        atomicAdd(&cnt[d4.x], 1);
        atomicAdd(&cnt[d4.y], 1);
        atomicAdd(&cnt[d4.z], 1);
        atomicAdd(&cnt[d4.w], 1);
    } else {
        int e = nv * 4 + (i - nv);      // tail edges (E not multiple of 4)
        if (e < E) atomicAdd(&cnt[ei[E + e]], 1);
    }
}

__global__ __launch_bounds__(1024, 1)
void scan_counts(const int* __restrict__ cnt, int* __restrict__ rowstart,
                 int* __restrict__ cursor, int N) {
    __shared__ int wsum[32];
    __shared__ int s_carry;
    const int tid = threadIdx.x, lane = tid & 31, wid = tid >> 5;
    if (tid == 0) s_carry = 0;
    __syncthreads();
    for (int base = 0; base < N; base += 4096) {
        int idx = base + tid * 4;
        int4 v = make_int4(-1, -1, -1, -1);   // -1 + 1 = 0 for out-of-range
        if (idx + 3 < N) v = *(const int4*)&cnt[idx];
        else {
            if (idx + 0 < N) v.x = cnt[idx + 0];
            if (idx + 1 < N) v.y = cnt[idx + 1];
            if (idx + 2 < N) v.z = cnt[idx + 2];
            if (idx + 3 < N) v.w = cnt[idx + 3];
        }
        v.x += 1; v.y += 1; v.z += 1; v.w += 1;   // self loops
        int tsum = v.x + v.y + v.z + v.w;
        int x = tsum;
        #pragma unroll
        for (int off = 1; off < 32; off <<= 1) {
            int y = __shfl_up_sync(0xFFFFFFFFu, x, off);
            if (lane >= off) x += y;
        }
        if (lane == 31) wsum[wid] = x;
        __syncthreads();
        if (wid == 0) {
            int w = wsum[lane];
            #pragma unroll
            for (int off = 1; off < 32; off <<= 1) {
                int y = __shfl_up_sync(0xFFFFFFFFu, w, off);
                if (lane >= off) w += y;
            }
            wsum[lane] = w;
        }
        __syncthreads();
        int carry = s_carry;
        int excl = carry + (wid > 0 ? wsum[wid - 1] : 0) + x - tsum;
        int e0 = excl;
        int e1 = e0 + v.x;
        int e2 = e1 + v.y;
        int e3 = e2 + v.z;
        if (idx + 3 < N) {
            *(int4*)&rowstart[idx] = make_int4(e0, e1, e2, e3);
            *(int4*)&cursor[idx]   = make_int4(e0, e1, e2, e3);
        } else {
            if (idx + 0 < N) { rowstart[idx + 0] = e0; cursor[idx + 0] = e0; }
            if (idx + 1 < N) { rowstart[idx + 1] = e1; cursor[idx + 1] = e1; }
            if (idx + 2 < N) { rowstart[idx + 2] = e2; cursor[idx + 2] = e2; }
            if (idx + 3 < N) { rowstart[idx + 3] = e3; cursor[idx + 3] = e3; }
        }
        __syncthreads();
        if (tid == 1023) s_carry = carry + wsum[31];
        __syncthreads();
    }
    if (tid == 0) rowstart[N] = s_carry;
}

__global__ void scatter_edges_v(const int* __restrict__ ei, int E, int N,
                                int* __restrict__ cursor,
                                int* __restrict__ sorted_src) {
    int i = blockIdx.x * blockDim.x + threadIdx.x;
    int nv = E >> 2;
    if (i < nv) {
        int4 s4 = *(const int4*)&ei[i * 4];
        int4 d4 = *(const int4*)&ei[E + i * 4];
        int p0 = atomicAdd(&cursor[d4.x], 1);
        int p1 = atomicAdd(&cursor[d4.y], 1);
        int p2 = atomicAdd(&cursor[d4.z], 1);
        int p3 = atomicAdd(&cursor[d4.w], 1);
        sorted_src[p0] = s4.x;
        sorted_src[p1] = s4.y;
        sorted_src[p2] = s4.z;
        sorted_src[p3] = s4.w;
    } else if (i < nv + N) {
        int d = i - nv;                 // self loop
        int p = atomicAdd(&cursor[d], 1);
        sorted_src[p] = d;
    } else {
        int e = nv * 4 + (i - nv - N);  // tail edges
        if (e < E) {
            int s = ei[e], d = ei[E + e];
            int p = atomicAdd(&cursor[d], 1);
            sorted_src[p] = s;
        }
    }
}

// ---------------------------------------------------------------------------
// HGEMM: C_h[M,Ncols] = A_h[M,128] @ W (WT[n][k] fp16), fp32 acc.
// mma.sync m16n8k16. Block 128x64, 8 warps (4M x 2N), warp tile 32x32.
// ---------------------------------------------------------------------------
#define AS_STRIDE 40
#define BS_STRIDE 136

__device__ __forceinline__ void mma16816(float* c, const unsigned int* a,
                                         unsigned int b0, unsigned int b1) {
    asm volatile(
        "mma.sync.aligned.m16n8k16.row.col.f32.f16.f16.f32 "
        "{%0,%1,%2,%3}, {%4,%5,%6,%7}, {%8,%9}, {%0,%1,%2,%3};"
        : "+f"(c[0]), "+f"(c[1]), "+f"(c[2]), "+f"(c[3])
        : "r"(a[0]), "r"(a[1]), "r"(a[2]), "r"(a[3]), "r"(b0), "r"(b1));
}

__global__ __launch_bounds__(256, 1)
void hgemm_k128(const __half* __restrict__ A, const __half* __restrict__ WT,
                __half* __restrict__ C, int M, int Ncols) {
    __shared__ __half As[128 * AS_STRIDE];
    __shared__ __half Bs[64 * BS_STRIDE];

    const int tid  = threadIdx.x;
    const int lane = tid & 31;
    const int wid  = tid >> 5;
    const int row0 = blockIdx.x * 128;
    const int col0 = blockIdx.y * 64;
    const int wm = (wid & 3) * 32;
    const int wn = (wid >> 2) * 32;

    {
        int n = tid >> 2;
        int p = (tid & 3) * 32;
        const uint4* src = (const uint4*)&WT[(size_t)(col0 + n) * 128 + p];
        uint4* dst = (uint4*)&Bs[n * BS_STRIDE + p];
        dst[0] = src[0]; dst[1] = src[1]; dst[2] = src[2]; dst[3] = src[3];
    }

    float acc[2][4][4];
    #pragma unroll
    for (int mt = 0; mt < 2; mt++)
        #pragma unroll
        for (int nt = 0; nt < 4; nt++)
            #pragma unroll
            for (int q = 0; q < 4; q++) acc[mt][nt][q] = 0.0f;

    const int arow = tid >> 1;
    const int acol = (tid & 1) * 16;
    const int frow = lane >> 2;
    const int fcol = 2 * (lane & 3);

    for (int kc = 0; kc < 128; kc += 32) {
        uint4 v0 = make_uint4(0, 0, 0, 0), v1 = make_uint4(0, 0, 0, 0);
        int gr = row0 + arow;
        if (gr < M) {
            const uint4* s = (const uint4*)&A[(size_t)gr * 128 + kc + acol];
            v0 = s[0]; v1 = s[1];
        }
        __syncthreads();
        *(uint4*)&As[arow * AS_STRIDE + acol]     = v0;
        *(uint4*)&As[arow * AS_STRIDE + acol + 8] = v1;
        __syncthreads();

        #pragma unroll
        for (int kk = 0; kk < 32; kk += 16) {
            unsigned int a[2][4];
            #pragma unroll
            for (int mt = 0; mt < 2; mt++) {
                int r = wm + mt * 16 + frow;
                int c = kk + fcol;
                a[mt][0] = *(const unsigned int*)&As[r * AS_STRIDE + c];
                a[mt][1] = *(const unsigned int*)&As[(r + 8) * AS_STRIDE + c];
                a[mt][2] = *(const unsigned int*)&As[r * AS_STRIDE + c + 8];
                a[mt][3] = *(const unsigned int*)&As[(r + 8) * AS_STRIDE + c + 8];
            }
            #pragma unroll
            for (int nt = 0; nt < 4; nt++) {
                int n = wn + nt * 8 + frow;
                int ck = kc + kk + fcol;
                unsigned int b0 = *(const unsigned int*)&Bs[n * BS_STRIDE + ck];
                unsigned int b1 = *(const unsigned int*)&Bs[n * BS_STRIDE + ck + 8];
                mma16816(acc[0][nt], a[0], b0, b1);
                mma16816(acc[1][nt], a[1], b0, b1);
            }
        }
    }

    #pragma unroll
    for (int mt = 0; mt < 2; mt++) {
        int r = row0 + wm + mt * 16 + frow;
        #pragma unroll
        for (int nt = 0; nt < 4; nt++) {
            int c = col0 + wn + nt * 8 + fcol;
            if (r < M) {
                __half2 h = __floats2half2_rn(acc[mt][nt][0], acc[mt][nt][1]);
                *(__half2*)&C[(size_t)r * Ncols + c] = h;
            }
            if (r + 8 < M) {
                __half2 h = __floats2half2_rn(acc[mt][nt][2], acc[mt][nt][3]);
                *(__half2*)&C[(size_t)(r + 8) * Ncols + c] = h;
            }
        }
    }
}

// ---------------------------------------------------------------------------
// Node attention terms: warp per node, vectorized fp16 loads.
// ---------------------------------------------------------------------------
__global__ __launch_bounds__(256)
void node_alpha1(const __half* __restrict__ h,
                 const float* __restrict__ a_src,
                 const float* __restrict__ a_dst,
                 float* __restrict__ al_s,
                 float* __restrict__ al_d, int N) {
    int w = (blockIdx.x * blockDim.x + threadIdx.x) >> 5;
    int lane = threadIdx.x & 31;
    if (w >= N) return;
    uint2 raw = *(const uint2*)&h[(size_t)w * 128 + lane * 4];
    float2 f0 = __half22float2(*(const __half2*)&raw.x);
    float2 f1 = __half22float2(*(const __half2*)&raw.y);
    float4 asv = *(const float4*)&a_src[lane * 4];
    float4 adv = *(const float4*)&a_dst[lane * 4];
    float ps = f0.x * asv.x + f0.y * asv.y + f1.x * asv.z + f1.y * asv.w;
    float pd = f0.x * adv.x + f0.y * adv.y + f1.x * adv.z + f1.y * adv.w;
    #pragma unroll
    for (int off = 4; off > 0; off >>= 1) {
        ps += __shfl_xor_sync(0xFFFFFFFFu, ps, off);
        pd += __shfl_xor_sync(0xFFFFFFFFu, pd, off);
    }
    if ((lane & 7) == 0) {
        int hd = lane >> 3;
        al_s[w * 4 + hd] = ps;
        al_d[w * 4 + hd] = pd;
    }
}

__global__ __launch_bounds__(256)
void node_alpha2(const __half* __restrict__ h,
                 const float* __restrict__ a_src,
                 const float* __restrict__ a_dst,
                 float* __restrict__ al_s,
                 float* __restrict__ al_d, int N) {
    int w = (blockIdx.x * blockDim.x + threadIdx.x) >> 5;
    int lane = threadIdx.x & 31;
    if (w >= N) return;
    uint4 raw = *(const uint4*)&h[(size_t)w * 256 + lane * 8];
    float2 f0 = __half22float2(*(const __half2*)&raw.x);
    float2 f1 = __half22float2(*(const __half2*)&raw.y);
    float2 f2 = __half22float2(*(const __half2*)&raw.z);
    float2 f3 = __half22float2(*(const __half2*)&raw.w);
    float4 s0 = *(const float4*)&a_src[lane * 8];
    float4 s1 = *(const float4*)&a_src[lane * 8 + 4];
    float4 d0 = *(const float4*)&a_dst[lane * 8];
    float4 d1 = *(const float4*)&a_dst[lane * 8 + 4];
    float ps = f0.x * s0.x + f0.y * s0.y + f1.x * s0.z + f1.y * s0.w
             + f2.x * s1.x + f2.y * s1.y + f3.x * s1.z + f3.y * s1.w;
    float pd = f0.x * d0.x + f0.y * d0.y + f1.x * d0.z + f1.y * d0.w
             + f2.x * d1.x + f2.y * d1.y + f3.x * d1.z + f3.y * d1.w;
    #pragma unroll
    for (int off = 16; off > 0; off >>= 1) {
        ps += __shfl_xor_sync(0xFFFFFFFFu, ps, off);
        pd += __shfl_xor_sync(0xFFFFFFFFu, pd, off);
    }
    if (lane == 0) {
        al_s[w] = ps;
        al_d[w] = pd;
    }
}

// ---------------------------------------------------------------------------
// Layer-1 fused gather, MLP=4. fp16 out + bias + relu.
// ---------------------------------------------------------------------------
__global__ __launch_bounds__(256)
void gather_agg1(const int* __restrict__ rowstart, const int* __restrict__ ssrc,
                 const float* __restrict__ als, const float* __restrict__ ald,
                 const __half* __restrict__ hlin, const float* __restrict__ bias,
                 __half* __restrict__ outp, int N) {
    int w = (blockIdx.x * blockDim.x + threadIdx.x) >> 5;
    int lane = threadIdx.x & 31;
    if (w >= N) return;
    const int beg = rowstart[w];
    const int end = rowstart[w + 1];
    const int head = lane >> 3;
    const float ad_h = ald[w * 4 + head];

    float ssum = 0.f;
    float4 acc = make_float4(0.f, 0.f, 0.f, 0.f);

    int j = beg;
    for (; j + 4 <= end; j += 4) {
        int sn0 = ssrc[j], sn1 = ssrc[j + 1], sn2 = ssrc[j + 2], sn3 = ssrc[j + 3];
        float al0 = als[sn0 * 4 + head];
        float al1 = als[sn1 * 4 + head];
        float al2 = als[sn2 * 4 + head];
        float al3 = als[sn3 * 4 + head];
        uint2 r0 = *(const uint2*)&hlin[(size_t)sn0 * 128 + lane * 4];
        uint2 r1 = *(const uint2*)&hlin[(size_t)sn1 * 128 + lane * 4];
        uint2 r2 = *(const uint2*)&hlin[(size_t)sn2 * 128 + lane * 4];
        uint2 r3 = *(const uint2*)&hlin[(size_t)sn3 * 128 + lane * 4];
        float e0 = __expf(lrelu(al0 + ad_h));
        float e1 = __expf(lrelu(al1 + ad_h));
        float e2 = __expf(lrelu(al2 + ad_h));
        float e3 = __expf(lrelu(al3 + ad_h));
        ssum += (e0 + e1) + (e2 + e3);
        float2 a, b;
        a = __half22float2(*(const __half2*)&r0.x);
        b = __half22float2(*(const __half2*)&r0.y);
        acc.x = fmaf(e0, a.x, acc.x); acc.y = fmaf(e0, a.y, acc.y);
        acc.z = fmaf(e0, b.x, acc.z); acc.w = fmaf(e0, b.y, acc.w);
        a = __half22float2(*(const __half2*)&r1.x);
        b = __half22float2(*(const __half2*)&r1.y);
        acc.x = fmaf(e1, a.x, acc.x); acc.y = fmaf(e1, a.y, acc.y);
        acc.z = fmaf(e1, b.x, acc.z); acc.w = fmaf(e1, b.y, acc.w);
        a = __half22float2(*(const __half2*)&r2.x);
        b = __half22float2(*(const __half2*)&r2.y);
        acc.x = fmaf(e2, a.x, acc.x); acc.y = fmaf(e2, a.y, acc.y);
        acc.z = fmaf(e2, b.x, acc.z); acc.w = fmaf(e2, b.y, acc.w);
        a = __half22float2(*(const __half2*)&r3.x);
        b = __half22float2(*(const __half2*)&r3.y);
        acc.x = fmaf(e3, a.x, acc.x); acc.y = fmaf(e3, a.y, acc.y);
        acc.z = fmaf(e3, b.x, acc.z); acc.w = fmaf(e3, b.y, acc.w);
    }
    for (; j < end; j++) {
        int sn = ssrc[j];
        float e = __expf(lrelu(als[sn * 4 + head] + ad_h));
        uint2 r = *(const uint2*)&hlin[(size_t)sn * 128 + lane * 4];
        ssum += e;
        float2 a = __half22float2(*(const __half2*)&r.x);
        float2 b = __half22float2(*(const __half2*)&r.y);
        acc.x = fmaf(e, a.x, acc.x); acc.y = fmaf(e, a.y, acc.y);
        acc.z = fmaf(e, b.x, acc.z); acc.w = fmaf(e, b.y, acc.w);
    }
    const float inv = 1.0f / (ssum + 1e-16f);
    float4 bb = *(const float4*)&bias[lane * 4];
    acc.x = fmaxf(fmaf(acc.x, inv, bb.x), 0.f);
    acc.y = fmaxf(fmaf(acc.y, inv, bb.y), 0.f);
    acc.z = fmaxf(fmaf(acc.z, inv, bb.z), 0.f);
    acc.w = fmaxf(fmaf(acc.w, inv, bb.w), 0.f);
    __half2 h0 = __floats2half2_rn(acc.x, acc.y);
    __half2 h1 = __floats2half2_rn(acc.z, acc.w);
    uint2 u;
    u.x = *(unsigned int*)&h0;
    u.y = *(unsigned int*)&h1;
    *(uint2*)&outp[(size_t)w * 128 + lane * 4] = u;
}

// ---------------------------------------------------------------------------
// Layer-2 fused gather, MLP=4. fp32 out.
// ---------------------------------------------------------------------------
__global__ __launch_bounds__(256)
void gather_agg2(const int* __restrict__ rowstart, const int* __restrict__ ssrc,
                 const float* __restrict__ als, const float* __restrict__ ald,
                 const __half* __restrict__ hlin, const float* __restrict__ bias,
                 float* __restrict__ outp, int N) {
    int w = (blockIdx.x * blockDim.x + threadIdx.x) >> 5;
    int lane = threadIdx.x & 31;
    if (w >= N) return;
    const int beg = rowstart[w];
    const int end = rowstart[w + 1];
    const float ad = ald[w];

    float ssum = 0.f;
    float4 a0 = make_float4(0.f, 0.f, 0.f, 0.f);
    float4 a1 = make_float4(0.f, 0.f, 0.f, 0.f);

    int j = beg;
    for (; j + 4 <= end; j += 4) {
        int sn0 = ssrc[j], sn1 = ssrc[j + 1], sn2 = ssrc[j + 2], sn3 = ssrc[j + 3];
        float al0 = als[sn0], al1 = als[sn1], al2 = als[sn2], al3 = als[sn3];
        uint4 r0 = *(const uint4*)&hlin[(size_t)sn0 * 256 + lane * 8];
        uint4 r1 = *(const uint4*)&hlin[(size_t)sn1 * 256 + lane * 8];
        uint4 r2 = *(const uint4*)&hlin[(size_t)sn2 * 256 + lane * 8];
        uint4 r3 = *(const uint4*)&hlin[(size_t)sn3 * 256 + lane * 8];
        float e0 = __expf(lrelu(al0 + ad));
        float e1 = __expf(lrelu(al1 + ad));
        float e2 = __expf(lrelu(al2 + ad));
        float e3 = __expf(lrelu(al3 + ad));
        ssum += (e0 + e1) + (e2 + e3);
        #define ACC8(rv, ev)                                                    \
        {                                                                       \
            float2 f0 = __half22float2(*(const __half2*)&rv.x);                 \
            float2 f1 = __half22float2(*(const __half2*)&rv.y);                 \
            float2 f2 = __half22float2(*(const __half2*)&rv.z);                 \
            float2 f3 = __half22float2(*(const __half2*)&rv.w);                 \
            a0.x = fmaf(ev, f0.x, a0.x); a0.y = fmaf(ev, f0.y, a0.y);           \
            a0.z = fmaf(ev, f1.x, a0.z); a0.w = fmaf(ev, f1.y, a0.w);           \
            a1.x = fmaf(ev, f2.x, a1.x); a1.y = fmaf(ev, f2.y, a1.y);           \
            a1.z = fmaf(ev, f3.x, a1.z); a1.w = fmaf(ev, f3.y, a1.w);           \
        }
        ACC8(r0, e0)
        ACC8(r1, e1)
        ACC8(r2, e2)
        ACC8(r3, e3)
    }
    for (; j < end; j++) {
        int sn = ssrc[j];
        float e = __expf(lrelu(als[sn] + ad));
        uint4 r = *(const uint4*)&hlin[(size_t)sn * 256 + lane * 8];
        ssum += e;
        ACC8(r, e)
    }
    #undef ACC8
    const float inv = 1.0f / (ssum + 1e-16f);
    float4 b0 = *(const float4*)&bias[lane * 8];
    float4 b1v = *(const float4*)&bias[lane * 8 + 4];
    a0.x = fmaf(a0.x, inv, b0.x);
    a0.y = fmaf(a0.y, inv, b0.y);
    a0.z = fmaf(a0.z, inv, b0.z);
    a0.w = fmaf(a0.w, inv, b0.w);
    a1.x = fmaf(a1.x, inv, b1v.x);
    a1.y = fmaf(a1.y, inv, b1v.y);
    a1.z = fmaf(a1.z, inv, b1v.z);
    a1.w = fmaf(a1.w, inv, b1v.w);
    float* op = &outp[(size_t)w * 256 + lane * 8];
    *(float4*)&op[0] = a0;
    *(float4*)&op[4] = a1;
}

// ---------------------------------------------------------------------------
// Launch
// ---------------------------------------------------------------------------
extern "C" void kernel_launch(void* const* d_in, const int* in_sizes, int n_in,
                              void* d_out, int out_size) {
    const float* x   = (const float*)d_in[0];
    const int*   ei  = (const int*)d_in[1];
    const float* W1  = (const float*)d_in[2];
    const float* as1 = (const float*)d_in[3];
    const float* ad1 = (const float*)d_in[4];
    const float* b1  = (const float*)d_in[5];
    const float* W2  = (const float*)d_in[6];
    const float* as2 = (const float*)d_in[7];
    const float* ad2 = (const float*)d_in[8];
    const float* b2  = (const float*)d_in[9];
    float* out = (float*)d_out;

    const int N = in_sizes[0] / 128;   // 50000
    const int E = in_sizes[1] / 2;     // 1600000

    float *als1p, *ald1p, *als2p, *ald2p;
    __half *xh, *wt1h, *wt2h, *hlin1, *agg1h, *hlin2;
    int *cntp, *rowp, *curp, *ssrcp;
    cudaGetSymbolAddress((void**)&xh,    g_xh);
    cudaGetSymbolAddress((void**)&wt1h,  g_wt1h);
    cudaGetSymbolAddress((void**)&wt2h,  g_wt2h);
    cudaGetSymbolAddress((void**)&hlin1, g_hlin1);
    cudaGetSymbolAddress((void**)&als1p, g_als1);
    cudaGetSymbolAddress((void**)&ald1p, g_ald1);
    cudaGetSymbolAddress((void**)&agg1h, g_agg1h);
    cudaGetSymbolAddress((void**)&hlin2, g_hlin2);
    cudaGetSymbolAddress((void**)&als2p, g_als2);
    cudaGetSymbolAddress((void**)&ald2p, g_ald2);
    cudaGetSymbolAddress((void**)&cntp,  g_count);
    cudaGetSymbolAddress((void**)&rowp,  g_rowstart);
    cudaGetSymbolAddress((void**)&curp,  g_cursor);
    cudaGetSymbolAddress((void**)&ssrcp, g_sorted_src);

    static cudaStream_t s2 = nullptr;
    static cudaEvent_t ev_fork = nullptr, ev_csr = nullptr;
    if (s2 == nullptr) {
        cudaStreamCreateWithFlags(&s2, cudaStreamNonBlocking);
        cudaEventCreateWithFlags(&ev_fork, cudaEventDisableTiming);
        cudaEventCreateWithFlags(&ev_csr,  cudaEventDisableTiming);
    }

    const int NW_BLOCKS = (N * 32 + 255) / 256;
    const int HIST_THREADS = (E >> 2) + (E & 3);
    const int SCAT_THREADS = (E >> 2) + N + (E & 3);

    // --- fork: vectorized CSR build on s2 ---
    cudaEventRecord(ev_fork, 0);
    cudaStreamWaitEvent(s2, ev_fork, 0);
    cudaMemsetAsync(cntp, 0, (size_t)N * sizeof(int), s2);
    hist_dst_v<<<(HIST_THREADS + 255) / 256, 256, 0, s2>>>(ei, E, cntp);
    scan_counts<<<1, 1024, 0, s2>>>(cntp, rowp, curp, N);
    scatter_edges_v<<<(SCAT_THREADS + 255) / 256, 256, 0, s2>>>(ei, E, N, curp, ssrcp);
    cudaEventRecord(ev_csr, s2);

    // --- main stream: conversions + GEMM1 + alpha1 (exact R6 chain) ---
    cvt_f2h<<<(N * 128 / 4 + 255) / 256, 256>>>(x, xh, N * 128 / 4);
    cvt_wts<<<(128 * 128 + 256 * 128 + 255) / 256, 256>>>(W1, wt1h, W2, wt2h);
    {
        dim3 grid((N + 127) / 128, 2);
        hgemm_k128<<<grid, 256>>>(xh, wt1h, hlin1, N, 128);
    }
    node_alpha1<<<NW_BLOCKS, 256>>>(hlin1, as1, ad1, als1p, ald1p, N);

    // --- join CSR; single-kernel gathers / GEMM2 chain ---
    cudaStreamWaitEvent(0, ev_csr, 0);
    gather_agg1<<<NW_BLOCKS, 256>>>(rowp, ssrcp, als1p, ald1p, hlin1, b1, agg1h, N);
    {
        dim3 grid((N + 127) / 128, 4);
        hgemm_k128<<<grid, 256>>>(agg1h, wt2h, hlin2, N, 256);
    }
    node_alpha2<<<NW_BLOCKS, 256>>>(hlin2, as2, ad2, als2p, ald2p, N);
    gather_agg2<<<NW_BLOCKS, 256>>>(rowp, ssrcp, als2p, ald2p, hlin2, b2, out, N);
}